// round 12
// baseline (speedup 1.0000x reference)
#include <cuda_runtime.h>

// SNN XOR net — streaming-store via intrinsic (combines R10 + R11 wins).
// Arithmetic byte-identical to R10/R11: FSET spike 1.0/0.0, beta as FFMA
// src1-immediate (bit-exact commute), reset FFMA-imm, acc fma chain in h order.
// vs R11: __stcs intrinsic instead of inline asm -> ptxas keeps folded [R+imm]
// store addressing and the 56-reg allocation (R11's asm forced regs to 72).
// Launch: block 128, grid 2048, 30KB dynamic-smem ballast (reserved by launch
// config; pins 7 blocks/SM -> wave=1036, 1.98 waves, 98.8% fill).

#define T_STEPS 20
#define THR 1.0f

__device__ __forceinline__ float fset_gt(float a, float b) {
    float d;
    asm("set.gt.f32.f32 %0, %1, %2;" : "=f"(d) : "f"(a), "f"(b));
    return d;  // 1.0f if a > b else 0.0f
}

template <int BQ>   // BQ = B/4 groups; BQ==0 means runtime B
__global__ void __launch_bounds__(128, 7) snn_xornet_kernel(
    const float* __restrict__ x,    // [B,2]
    const float* __restrict__ w1,   // [4,2]
    const float* __restrict__ w2,   // [1,4]
    float* __restrict__ out,        // [T,B]
    int B)
{
    const int i = blockIdx.x * blockDim.x + threadIdx.x;  // group of 4 elems
    if (i * 4 >= B) return;

    float w1r[4][2];
#pragma unroll
    for (int h = 0; h < 4; h++) {
        w1r[h][0] = __ldg(&w1[2 * h + 0]);
        w1r[h][1] = __ldg(&w1[2 * h + 1]);
    }
    float w2r[4];
#pragma unroll
    for (int h = 0; h < 4; h++) w2r[h] = __ldg(&w2[h]);

    const float4 xa = reinterpret_cast<const float4*>(x)[2 * i + 0];
    const float4 xb = reinterpret_cast<const float4*>(x)[2 * i + 1];
    const float xs[4][2] = {{xa.x, xa.y}, {xa.z, xa.w}, {xb.x, xb.y}, {xb.z, xb.w}};

    // cur = x @ w1^T (identical rounding to all passing kernels)
    float cur[4][4];
#pragma unroll
    for (int j = 0; j < 4; j++)
#pragma unroll
        for (int h = 0; h < 4; h++)
            cur[j][h] = fmaf(xs[j][0], w1r[h][0], xs[j][1] * w1r[h][1]);

    float m1[4][4], s1[4][4];
    float m2[4], s2[4];
#pragma unroll
    for (int j = 0; j < 4; j++) {
        m2[j] = 0.0f; s2[j] = 0.0f;
#pragma unroll
        for (int h = 0; h < 4; h++) { m1[j][h] = 0.0f; s1[j][h] = 0.0f; }
    }

    const int bq = (BQ > 0) ? BQ : (B >> 2);
    float4* out4 = reinterpret_cast<float4*>(out) + i;

#pragma unroll
    for (int t = 0; t < T_STEPS; t++) {
        float4 v;
#pragma unroll
        for (int j = 0; j < 4; j++) {
            float acc = 0.0f;
#pragma unroll
            for (int h = 0; h < 4; h++) {
                // beta as src1 IMMEDIATE (commuted, bit-identical): FFMA-imm rt 1
                float m = fmaf(m1[j][h], 0.9f, cur[j][h]);
                m = fmaf(s1[j][h], -1.0f, m);        // == m - s (bit-exact), imm
                m1[j][h] = m;
                const float sp = fset_gt(m, THR);    // FSET: 1.0/0.0
                s1[j][h] = sp;
                acc = fmaf(sp, w2r[h], acc);         // exact: +w2 or +0
            }
            float mo = fmaf(m2[j], 0.9f, acc);       // imm-form
            mo = fmaf(s2[j], -1.0f, mo);             // == mo - s2 (bit-exact)
            m2[j] = mo;
            const float so = fset_gt(mo, THR);
            s2[j] = so;
            if (j == 0) v.x = so;
            else if (j == 1) v.y = so;
            else if (j == 2) v.z = so;
            else v.w = so;
        }
        __stcs(out4 + (size_t)t * bq, v);            // STG.E.128.CS, folded addr
    }
}

extern "C" void kernel_launch(void* const* d_in, const int* in_sizes, int n_in,
                              void* d_out, int out_size) {
    const float* x  = (const float*)d_in[0];   // [B,2]
    const float* w1 = (const float*)d_in[1];   // [4,2]
    const float* w2 = (const float*)d_in[2];   // [1,4]
    float* out = (float*)d_out;                // [T,B,1]

    const int B = in_sizes[0] / 2;
    const int threads = 128;
    const int blocks = (B / 4 + threads - 1) / threads;
    const size_t ballast = 30 * 1024;          // reserved at launch: 7 blocks/SM
    if (B == 1048576) {
        snn_xornet_kernel<262144><<<blocks, threads, ballast>>>(x, w1, w2, out, B);
    } else {
        snn_xornet_kernel<0><<<blocks, threads, ballast>>>(x, w1, w2, out, B);
    }
}

// round 13
// speedup vs baseline: 1.1198x; 1.1198x over previous
#include <cuda_runtime.h>

// SNN XOR net — .cs streaming + immediate-offset stores.
// Arithmetic byte-identical to R10-R12 (FSET spike, beta/reset as FFMA-imm).
// New: the 20 timestep stores are emitted as st.global.cs.v4 [base + IMM]
// with compile-time byte offsets t*BQ*16 ("n" asm constraint, manual unroll),
// so ONE base address register serves all stores — recovers the register/
// addressing profile that the __stcs/.cs pointer forms lost (regs 72 -> ~56),
// while keeping the evict-first policy that gave R11 the best wall time.
// Launch: 128 thr x 2048 blocks + 30KB ballast -> 7 blocks/SM, 1.98 waves.

#define T_STEPS 20
#define THR 1.0f

__device__ __forceinline__ float fset_gt(float a, float b) {
    float d;
    asm("set.gt.f32.f32 %0, %1, %2;" : "=f"(d) : "f"(a), "f"(b));
    return d;  // 1.0f if a > b else 0.0f
}

template <int BQ>   // BQ = B/4 groups (compile-time); BQ==0 -> runtime path
__global__ void __launch_bounds__(128, 7) snn_xornet_kernel(
    const float* __restrict__ x,    // [B,2]
    const float* __restrict__ w1,   // [4,2]
    const float* __restrict__ w2,   // [1,4]
    float* __restrict__ out,        // [T,B]
    int B)
{
    const int i = blockIdx.x * blockDim.x + threadIdx.x;  // group of 4 elems
    if (i * 4 >= B) return;

    float w1r[4][2];
#pragma unroll
    for (int h = 0; h < 4; h++) {
        w1r[h][0] = __ldg(&w1[2 * h + 0]);
        w1r[h][1] = __ldg(&w1[2 * h + 1]);
    }
    float w2r[4];
#pragma unroll
    for (int h = 0; h < 4; h++) w2r[h] = __ldg(&w2[h]);

    const float4 xa = reinterpret_cast<const float4*>(x)[2 * i + 0];
    const float4 xb = reinterpret_cast<const float4*>(x)[2 * i + 1];
    const float xs[4][2] = {{xa.x, xa.y}, {xa.z, xa.w}, {xb.x, xb.y}, {xb.z, xb.w}};

    // cur = x @ w1^T (identical rounding to all passing kernels)
    float cur[4][4];
#pragma unroll
    for (int j = 0; j < 4; j++)
#pragma unroll
        for (int h = 0; h < 4; h++)
            cur[j][h] = fmaf(xs[j][0], w1r[h][0], xs[j][1] * w1r[h][1]);

    float m1[4][4], s1[4][4];
    float m2[4], s2[4];
#pragma unroll
    for (int j = 0; j < 4; j++) {
        m2[j] = 0.0f; s2[j] = 0.0f;
#pragma unroll
        for (int h = 0; h < 4; h++) { m1[j][h] = 0.0f; s1[j][h] = 0.0f; }
    }

    float4* base = reinterpret_cast<float4*>(out) + i;   // single base register

    // One timestep of the bit-exact recurrence; stores via immediate offset.
#define SNN_STEP(T_)                                                          \
    {                                                                         \
        float4 v;                                                             \
        _Pragma("unroll")                                                     \
        for (int j = 0; j < 4; j++) {                                         \
            float acc = 0.0f;                                                 \
            _Pragma("unroll")                                                 \
            for (int h = 0; h < 4; h++) {                                     \
                float m = fmaf(m1[j][h], 0.9f, cur[j][h]);                    \
                m = fmaf(s1[j][h], -1.0f, m);                                 \
                m1[j][h] = m;                                                 \
                const float sp = fset_gt(m, THR);                             \
                s1[j][h] = sp;                                                \
                acc = fmaf(sp, w2r[h], acc);                                  \
            }                                                                 \
            float mo = fmaf(m2[j], 0.9f, acc);                                \
            mo = fmaf(s2[j], -1.0f, mo);                                      \
            m2[j] = mo;                                                       \
            const float so = fset_gt(mo, THR);                                \
            s2[j] = so;                                                       \
            if (j == 0) v.x = so;                                             \
            else if (j == 1) v.y = so;                                        \
            else if (j == 2) v.z = so;                                        \
            else v.w = so;                                                    \
        }                                                                     \
        if (BQ > 0) {                                                         \
            asm volatile(                                                     \
                "st.global.cs.v4.f32 [%0+%5], {%1, %2, %3, %4};"             \
                :: "l"(base), "f"(v.x), "f"(v.y), "f"(v.z), "f"(v.w),         \
                   "n"((long)(T_) * (long)BQ * 16L)                           \
                : "memory");                                                  \
        } else {                                                              \
            __stcs(base + (size_t)(T_) * (size_t)(B >> 2), v);                \
        }                                                                     \
    }

    SNN_STEP(0)  SNN_STEP(1)  SNN_STEP(2)  SNN_STEP(3)  SNN_STEP(4)
    SNN_STEP(5)  SNN_STEP(6)  SNN_STEP(7)  SNN_STEP(8)  SNN_STEP(9)
    SNN_STEP(10) SNN_STEP(11) SNN_STEP(12) SNN_STEP(13) SNN_STEP(14)
    SNN_STEP(15) SNN_STEP(16) SNN_STEP(17) SNN_STEP(18) SNN_STEP(19)
#undef SNN_STEP
}

extern "C" void kernel_launch(void* const* d_in, const int* in_sizes, int n_in,
                              void* d_out, int out_size) {
    const float* x  = (const float*)d_in[0];   // [B,2]
    const float* w1 = (const float*)d_in[1];   // [4,2]
    const float* w2 = (const float*)d_in[2];   // [1,4]
    float* out = (float*)d_out;                // [T,B,1]

    const int B = in_sizes[0] / 2;
    const int threads = 128;
    const int blocks = (B / 4 + threads - 1) / threads;
    const size_t ballast = 30 * 1024;          // 7 blocks/SM -> 98.8% fill
    if (B == 1048576) {
        snn_xornet_kernel<262144><<<blocks, threads, ballast>>>(x, w1, w2, out, B);
    } else {
        snn_xornet_kernel<0><<<blocks, threads, ballast>>>(x, w1, w2, out, B);
    }
}